// round 1
// baseline (speedup 1.0000x reference)
#include <cuda_runtime.h>
#include <math.h>

#define N_MAX 100000
#define E_MAX 1200000
#define F 64

// ---------------- scratch (static device globals; no runtime alloc) --------
__device__ float g_xs [(size_t)N_MAX * F];   // dis[i] * (h @ W) rows
__device__ float g_acc[(size_t)N_MAX * F];   // accumulation / layer output
__device__ float g_cnt[N_MAX];               // in-degree counts (float, exact)
__device__ float g_dis[N_MAX];               // rsqrt(deg)
__device__ float g_emb[F];                   // column sums for mean pool
__device__ float g_gf [8];                   // global feature sums
__device__ int   g_is64;                     // edge_index dtype flag

// ---------------- helpers ---------------------------------------------------
__device__ __forceinline__ void load_edge(const void* eidx, int e, int E,
                                          int n, int& s, int& d) {
    if (g_is64) {
        const long long* p = (const long long*)eidx;
        s = (int)p[e];
        d = (int)p[(size_t)E + e];
    } else {
        const int* p = (const int*)eidx;
        s = p[e];
        d = p[E + e];
    }
    // defensive clamp (protects against dtype misdetection -> no illegal access)
    s = min(max(s, 0), n - 1);
    d = min(max(d, 0), n - 1);
}

// ---------------- kernels ---------------------------------------------------

// detect int64 vs int32 edge_index: int64 little-endian small values => odd
// 32-bit words are all zero.
__global__ void detect_kernel(const unsigned int* p) {
    int is64 = 1;
    for (int i = 1; i < 64; i += 2)
        if (p[i] != 0u) { is64 = 0; break; }
    g_is64 = is64;
}

__global__ void zero_kernel(int n) {
    int i = blockIdx.x * blockDim.x + threadIdx.x;
    if (i < n)  g_cnt[i] = 0.0f;
    if (i < F)  g_emb[i] = 0.0f;
    if (i < 8)  g_gf[i]  = 0.0f;
}

__global__ void count_kernel(const void* eidx, int E, int n) {
    int e = blockIdx.x * blockDim.x + threadIdx.x;
    if (e >= E) return;
    int s, d;
    load_edge(eidx, e, E, n, s, d);
    atomicAdd(&g_cnt[d], 1.0f);
}

__global__ void finalize_deg_kernel(int n) {
    int i = blockIdx.x * blockDim.x + threadIdx.x;
    if (i < n) g_dis[i] = rsqrtf(g_cnt[i] + 1.0f);
}

// layer-1 transform: xs = dis*(x@W1); acc = dis*xs + b1.  4 nodes / block(256)
__global__ void xw1_kernel(const float* __restrict__ x,
                           const float* __restrict__ W1,
                           const float* __restrict__ b1, int n) {
    __shared__ float W1s[5 * F];
    __shared__ float xr[4 * 5];
    int base = blockIdx.x * 4;
    int tid  = threadIdx.x;
    for (int i = tid; i < 5 * F; i += 256) W1s[i] = W1[i];
    if (tid < 20) {
        int node = base + tid / 5;
        xr[tid] = (node < n) ? x[(size_t)node * 5 + (tid % 5)] : 0.0f;
    }
    __syncthreads();
    int nl   = tid >> 6;           // 0..3
    int col  = tid & 63;
    int node = base + nl;
    if (node >= n) return;
    float s = 0.0f;
#pragma unroll
    for (int k = 0; k < 5; k++) s += xr[nl * 5 + k] * W1s[k * F + col];
    float dn = g_dis[node];
    float xs = dn * s;
    g_xs [(size_t)node * F + col] = xs;
    g_acc[(size_t)node * F + col] = dn * xs + b1[col];
}

// edge scatter: acc[dst] += dis[dst] * xs[src].  16 threads/edge, red.v4.f32
__global__ void scatter_kernel(const void* eidx, int E, int n) {
    long long t = (long long)blockIdx.x * blockDim.x + threadIdx.x;
    int e = (int)(t >> 4);
    if (e >= E) return;
    int sub = (int)(t & 15);
    int s, d;
    load_edge(eidx, e, E, n, s, d);
    float dd = g_dis[d];
    float4 v = *(const float4*)&g_xs[(size_t)s * F + sub * 4];
    float* dst = &g_acc[(size_t)d * F + sub * 4];
    asm volatile("red.global.add.v4.f32 [%0], {%1,%2,%3,%4};"
                 :: "l"(dst), "f"(v.x * dd), "f"(v.y * dd),
                    "f"(v.z * dd), "f"(v.w * dd) : "memory");
}

// layer-2 transform (in place): h = relu(acc); xs = dis*(h@W2); acc = dis*xs+b2
// 64 nodes / block(256), register tile 4 nodes x 4 cols.
__global__ void xw2_kernel(const float* __restrict__ W2,
                           const float* __restrict__ b2, int n) {
    __shared__ float W2s[F * F];   // 16 KB
    __shared__ float hs [F * F];   // 16 KB
    int base = blockIdx.x * 64;
    int tid  = threadIdx.x;

    for (int i = tid; i < (F * F) / 4; i += 256)
        ((float4*)W2s)[i] = ((const float4*)W2)[i];
    for (int i = tid; i < (F * F) / 4; i += 256) {
        int node = base + (i >> 4);
        float4 v = make_float4(0.f, 0.f, 0.f, 0.f);
        if (node < n) v = ((const float4*)g_acc)[(size_t)node * 16 + (i & 15)];
        v.x = fmaxf(v.x, 0.f); v.y = fmaxf(v.y, 0.f);
        v.z = fmaxf(v.z, 0.f); v.w = fmaxf(v.w, 0.f);
        ((float4*)hs)[i] = v;
    }
    __syncthreads();

    int cg = tid & 15;   // col group: cols cg*4..cg*4+3
    int ng = tid >> 4;   // node group: nodes ng*4..ng*4+3
    float a[4][4];
#pragma unroll
    for (int i = 0; i < 4; i++)
#pragma unroll
        for (int j = 0; j < 4; j++) a[i][j] = 0.0f;

    const float4* W2v = (const float4*)W2s;
#pragma unroll 8
    for (int k = 0; k < F; k++) {
        float4 w = W2v[k * 16 + cg];
        float h0 = hs[(ng * 4 + 0) * F + k];
        float h1 = hs[(ng * 4 + 1) * F + k];
        float h2 = hs[(ng * 4 + 2) * F + k];
        float h3 = hs[(ng * 4 + 3) * F + k];
        a[0][0] += h0 * w.x; a[0][1] += h0 * w.y; a[0][2] += h0 * w.z; a[0][3] += h0 * w.w;
        a[1][0] += h1 * w.x; a[1][1] += h1 * w.y; a[1][2] += h1 * w.z; a[1][3] += h1 * w.w;
        a[2][0] += h2 * w.x; a[2][1] += h2 * w.y; a[2][2] += h2 * w.z; a[2][3] += h2 * w.w;
        a[3][0] += h3 * w.x; a[3][1] += h3 * w.y; a[3][2] += h3 * w.z; a[3][3] += h3 * w.w;
    }

    float4 b4 = *(const float4*)&b2[cg * 4];
#pragma unroll
    for (int i = 0; i < 4; i++) {
        int node = base + ng * 4 + i;
        if (node >= n) continue;
        float dn = g_dis[node];
        float4 xs4 = make_float4(a[i][0] * dn, a[i][1] * dn,
                                 a[i][2] * dn, a[i][3] * dn);
        *(float4*)&g_xs[(size_t)node * F + cg * 4] = xs4;
        float4 ac = make_float4(xs4.x * dn + b4.x, xs4.y * dn + b4.y,
                                xs4.z * dn + b4.z, xs4.w * dn + b4.w);
        *(float4*)&g_acc[(size_t)node * F + cg * 4] = ac;
    }
}

// column sums of relu(acc) -> g_emb (divide by N in final kernel)
__global__ void mean_kernel(int n) {
    __shared__ float s[256];
    size_t total  = (size_t)n * F;
    size_t stride = (size_t)gridDim.x * blockDim.x;
    float acc = 0.0f;
    for (size_t i = (size_t)blockIdx.x * blockDim.x + threadIdx.x; i < total; i += stride)
        acc += fmaxf(g_acc[i], 0.0f);
    s[threadIdx.x] = acc;
    __syncthreads();
    if (threadIdx.x < 64) {
        float v = s[threadIdx.x] + s[threadIdx.x + 64] +
                  s[threadIdx.x + 128] + s[threadIdx.x + 192];
        atomicAdd(&g_emb[threadIdx.x], v);   // (i & 63) == threadIdx.x & 63
    }
}

// global feature sums over x
__global__ void gfeat_kernel(const float* __restrict__ x, int n) {
    float s2 = 0, s3 = 0, s4 = 0, sm = 0, sl = 0, su = 0;
    int stride = gridDim.x * blockDim.x;
    for (int i = blockIdx.x * blockDim.x + threadIdx.x; i < n; i += stride) {
        const float* r = &x[(size_t)i * 5];
        float x0 = r[0], x1 = r[1], x2 = r[2], x3 = r[3], x4 = r[4];
        s2 += x2; s3 += x3; s4 += x4;
        float m = (x2 == 1.0f) ? 1.0f : 0.0f;
        sm += m; sl += x0 * m; su += x1 * m;
    }
#pragma unroll
    for (int o = 16; o > 0; o >>= 1) {
        s2 += __shfl_down_sync(0xffffffffu, s2, o);
        s3 += __shfl_down_sync(0xffffffffu, s3, o);
        s4 += __shfl_down_sync(0xffffffffu, s4, o);
        sm += __shfl_down_sync(0xffffffffu, sm, o);
        sl += __shfl_down_sync(0xffffffffu, sl, o);
        su += __shfl_down_sync(0xffffffffu, su, o);
    }
    if ((threadIdx.x & 31) == 0) {
        atomicAdd(&g_gf[0], s2); atomicAdd(&g_gf[1], s3);
        atomicAdd(&g_gf[2], s4); atomicAdd(&g_gf[3], sm);
        atomicAdd(&g_gf[4], sl); atomicAdd(&g_gf[5], su);
    }
}

// final MLP head
__global__ void final_kernel(const float* __restrict__ Wp1,
                             const float* __restrict__ bp1,
                             const float* __restrict__ Wp2,
                             const float* __restrict__ bp2,
                             const int* __restrict__ Tp,
                             const int* __restrict__ Tmp,
                             float* __restrict__ out, int n) {
    __shared__ float e[71];
    __shared__ float hid[32];
    int tid = threadIdx.x;
    if (tid < 64) e[tid] = g_emb[tid] / (float)n;
    if (tid == 64) {
        float nAND = g_gf[1], nOR = g_gf[2];
        e[64] = g_gf[0];
        e[65] = nAND;
        e[66] = nOR;
        e[67] = nAND + nOR;
        float msum = g_gf[3];
        float safe = fmaxf(msum, 1.0f);
        e[68] = (msum > 0.0f) ? g_gf[4] / safe : 0.0f;
        e[69] = (msum > 0.0f) ? g_gf[5] / safe : 0.0f;
        e[70] = (float)(*Tp) / (float)(*Tmp);
    }
    __syncthreads();
    if (tid < 32) {
        float a = bp1[tid];
        for (int k = 0; k < 71; k++) a += e[k] * Wp1[k * 32 + tid];
        hid[tid] = fmaxf(a, 0.0f);
    }
    __syncthreads();
    if (tid < 2) {
        float r = bp2[tid];
#pragma unroll
        for (int j = 0; j < 32; j++) r += hid[j] * Wp2[j * 2 + tid];
        out[tid] = 2.0f + 4.0f / (1.0f + expf(-r));
    }
}

// ---------------- launch ----------------------------------------------------
extern "C" void kernel_launch(void* const* d_in, const int* in_sizes, int n_in,
                              void* d_out, int out_size) {
    const float* x   = (const float*)d_in[0];
    const void*  ei  = d_in[1];
    const float* W1  = (const float*)d_in[2];
    const float* b1  = (const float*)d_in[3];
    const float* W2  = (const float*)d_in[4];
    const float* b2  = (const float*)d_in[5];
    const float* Wp1 = (const float*)d_in[6];
    const float* bp1 = (const float*)d_in[7];
    const float* Wp2 = (const float*)d_in[8];
    const float* bp2 = (const float*)d_in[9];
    const int*   Tp  = (const int*)d_in[10];
    const int*   Tmp = (const int*)d_in[11];
    float* out = (float*)d_out;

    int n = in_sizes[0] / 5;
    int E = in_sizes[1] / 2;

    zero_kernel<<<(n + 255) / 256, 256>>>(n);
    detect_kernel<<<1, 1>>>((const unsigned int*)ei);
    count_kernel<<<(E + 255) / 256, 256>>>(ei, E, n);
    finalize_deg_kernel<<<(n + 255) / 256, 256>>>(n);

    // layer 1
    xw1_kernel<<<(n + 3) / 4, 256>>>(x, W1, b1, n);
    {
        long long th = (long long)E * 16;
        scatter_kernel<<<(unsigned)((th + 255) / 256), 256>>>(ei, E, n);
    }
    // layer 2
    xw2_kernel<<<(n + 63) / 64, 256>>>(W2, b2, n);
    {
        long long th = (long long)E * 16;
        scatter_kernel<<<(unsigned)((th + 255) / 256), 256>>>(ei, E, n);
    }

    mean_kernel<<<512, 256>>>(n);
    gfeat_kernel<<<256, 256>>>(x, n);
    final_kernel<<<1, 128>>>(Wp1, bp1, Wp2, bp2, Tp, Tmp, out, n);
}

// round 2
// speedup vs baseline: 1.3251x; 1.3251x over previous
#include <cuda_runtime.h>
#include <math.h>

#define N_MAX 100000
#define E_MAX 1200000
#define F 64
#define SCAN_B 512

// ---------------- scratch (static device globals) --------------------------
__device__ float g_xs [(size_t)N_MAX * F];   // dis[i] * (h @ W) rows
__device__ float g_acc[(size_t)N_MAX * F];   // relu'd layer output
__device__ int   g_deg[N_MAX];               // in-degree counts / fill cursor
__device__ int   g_off[N_MAX + 1];           // CSR offsets (by dst)
__device__ int   g_blk[SCAN_B];              // scan block sums
__device__ int   g_srcs[E_MAX];              // CSR src lists
__device__ float g_dis[N_MAX];               // rsqrt(deg+1)
__device__ float g_emb[F];                   // column sums for mean pool
__device__ float g_gf [8];                   // global feature sums
__device__ int   g_is64;                     // edge_index dtype flag

// ---------------- helpers ---------------------------------------------------
__device__ __forceinline__ int load_dst(const void* eidx, int e, int E, int n) {
    int d = g_is64 ? (int)((const long long*)eidx)[(size_t)E + e]
                   : ((const int*)eidx)[E + e];
    return min(max(d, 0), n - 1);
}
__device__ __forceinline__ void load_edge(const void* eidx, int e, int E,
                                          int n, int& s, int& d) {
    if (g_is64) {
        const long long* p = (const long long*)eidx;
        s = (int)p[e];
        d = (int)p[(size_t)E + e];
    } else {
        const int* p = (const int*)eidx;
        s = p[e];
        d = p[E + e];
    }
    s = min(max(s, 0), n - 1);
    d = min(max(d, 0), n - 1);
}

// ---------------- CSR build -------------------------------------------------
__global__ void detect_kernel(const unsigned int* p) {
    int is64 = 1;
    for (int i = 1; i < 64; i += 2)
        if (p[i] != 0u) { is64 = 0; break; }
    g_is64 = is64;
}

__global__ void zero_kernel(int n) {
    int i = blockIdx.x * blockDim.x + threadIdx.x;
    if (i < n)  g_deg[i] = 0;
    if (i < F)  g_emb[i] = 0.0f;
    if (i < 8)  g_gf[i]  = 0.0f;
}

__global__ void count_kernel(const void* eidx, int E, int n) {
    int e = blockIdx.x * blockDim.x + threadIdx.x;
    if (e >= E) return;
    atomicAdd(&g_deg[load_dst(eidx, e, E, n)], 1);
}

__global__ void finalize_deg_kernel(int n) {
    int i = blockIdx.x * blockDim.x + threadIdx.x;
    if (i < n) g_dis[i] = rsqrtf((float)g_deg[i] + 1.0f);
}

// exclusive scan of g_deg into g_off (3-phase)
__global__ void scanA_kernel(int n) {
    __shared__ int sh[SCAN_B];
    int tid = threadIdx.x;
    int i = blockIdx.x * SCAN_B + tid;
    int v = (i < n) ? g_deg[i] : 0;
    sh[tid] = v;
    __syncthreads();
    for (int o = 1; o < SCAN_B; o <<= 1) {
        int t = (tid >= o) ? sh[tid - o] : 0;
        __syncthreads();
        sh[tid] += t;
        __syncthreads();
    }
    int incl = sh[tid];
    if (i < n) g_off[i] = incl - v;
    if (tid == SCAN_B - 1) g_blk[blockIdx.x] = incl;
}
__global__ void scanB_kernel(int nb) {
    __shared__ int sh[SCAN_B];
    int tid = threadIdx.x;
    int v = (tid < nb) ? g_blk[tid] : 0;
    sh[tid] = v;
    __syncthreads();
    for (int o = 1; o < SCAN_B; o <<= 1) {
        int t = (tid >= o) ? sh[tid - o] : 0;
        __syncthreads();
        sh[tid] += t;
        __syncthreads();
    }
    if (tid < nb) g_blk[tid] = sh[tid] - v;   // exclusive
}
__global__ void scanC_kernel(int n, int E) {
    int i = blockIdx.x * SCAN_B + threadIdx.x;
    if (i < n) {
        g_off[i] += g_blk[blockIdx.x];
        g_deg[i] = 0;                         // reset as fill cursor
    }
    if (i == 0) g_off[n] = E;
}

__global__ void fill_kernel(const void* eidx, int E, int n) {
    int e = blockIdx.x * blockDim.x + threadIdx.x;
    if (e >= E) return;
    int s, d;
    load_edge(eidx, e, E, n, s, d);
    int idx = g_off[d] + atomicAdd(&g_deg[d], 1);
    g_srcs[idx] = s;
}

// ---------------- dense transforms ------------------------------------------
// layer-1 transform: xs = dis*(x@W1).  4 nodes / block(256)
__global__ void xw1_kernel(const float* __restrict__ x,
                           const float* __restrict__ W1, int n) {
    __shared__ float W1s[5 * F];
    __shared__ float xr[4 * 5];
    int base = blockIdx.x * 4;
    int tid  = threadIdx.x;
    for (int i = tid; i < 5 * F; i += 256) W1s[i] = W1[i];
    if (tid < 20) {
        int node = base + tid / 5;
        xr[tid] = (node < n) ? x[(size_t)node * 5 + (tid % 5)] : 0.0f;
    }
    __syncthreads();
    int nl   = tid >> 6;
    int col  = tid & 63;
    int node = base + nl;
    if (node >= n) return;
    float s = 0.0f;
#pragma unroll
    for (int k = 0; k < 5; k++) s += xr[nl * 5 + k] * W1s[k * F + col];
    g_xs[(size_t)node * F + col] = g_dis[node] * s;
}

// layer-2 transform: xs = dis*(g_acc @ W2)  (g_acc already relu'd)
__global__ void xw2_kernel(const float* __restrict__ W2, int n) {
    __shared__ float W2s[F * F];
    __shared__ float hs [F * F];
    int base = blockIdx.x * 64;
    int tid  = threadIdx.x;

    for (int i = tid; i < (F * F) / 4; i += 256)
        ((float4*)W2s)[i] = ((const float4*)W2)[i];
    for (int i = tid; i < (F * F) / 4; i += 256) {
        int node = base + (i >> 4);
        float4 v = make_float4(0.f, 0.f, 0.f, 0.f);
        if (node < n) v = ((const float4*)g_acc)[(size_t)node * 16 + (i & 15)];
        ((float4*)hs)[i] = v;
    }
    __syncthreads();

    int cg = tid & 15;
    int ng = tid >> 4;
    float a[4][4];
#pragma unroll
    for (int i = 0; i < 4; i++)
#pragma unroll
        for (int j = 0; j < 4; j++) a[i][j] = 0.0f;

    const float4* W2v = (const float4*)W2s;
#pragma unroll 8
    for (int k = 0; k < F; k++) {
        float4 w = W2v[k * 16 + cg];
        float h0 = hs[(ng * 4 + 0) * F + k];
        float h1 = hs[(ng * 4 + 1) * F + k];
        float h2 = hs[(ng * 4 + 2) * F + k];
        float h3 = hs[(ng * 4 + 3) * F + k];
        a[0][0] += h0 * w.x; a[0][1] += h0 * w.y; a[0][2] += h0 * w.z; a[0][3] += h0 * w.w;
        a[1][0] += h1 * w.x; a[1][1] += h1 * w.y; a[1][2] += h1 * w.z; a[1][3] += h1 * w.w;
        a[2][0] += h2 * w.x; a[2][1] += h2 * w.y; a[2][2] += h2 * w.z; a[2][3] += h2 * w.w;
        a[3][0] += h3 * w.x; a[3][1] += h3 * w.y; a[3][2] += h3 * w.z; a[3][3] += h3 * w.w;
    }

#pragma unroll
    for (int i = 0; i < 4; i++) {
        int node = base + ng * 4 + i;
        if (node >= n) continue;
        float dn = g_dis[node];
        float4 xs4 = make_float4(a[i][0] * dn, a[i][1] * dn,
                                 a[i][2] * dn, a[i][3] * dn);
        *(float4*)&g_xs[(size_t)node * F + cg * 4] = xs4;
    }
}

// ---------------- CSR gather: acc = relu(dis*(sum_src xs + xs_self) + b) ----
// 16 lanes per node, float4 per lane. 16 nodes / block(256).
__global__ void gather_kernel(const float* __restrict__ b, int n) {
    int tid  = threadIdx.x;
    int sub  = tid & 15;
    int node = blockIdx.x * 16 + (tid >> 4);
    if (node >= n) return;

    int beg = g_off[node];
    int end = g_off[node + 1];
    float dn = g_dis[node];
    const float4* xsv = (const float4*)g_xs;

    float4 self = xsv[(size_t)node * 16 + sub];
    float sx = self.x, sy = self.y, sz = self.z, sw = self.w;

    int e = beg;
    for (; e + 2 <= end; e += 2) {
        int s0 = g_srcs[e];
        int s1 = g_srcs[e + 1];
        float4 v0 = xsv[(size_t)s0 * 16 + sub];
        float4 v1 = xsv[(size_t)s1 * 16 + sub];
        sx += v0.x + v1.x; sy += v0.y + v1.y;
        sz += v0.z + v1.z; sw += v0.w + v1.w;
    }
    if (e < end) {
        float4 v0 = xsv[(size_t)g_srcs[e] * 16 + sub];
        sx += v0.x; sy += v0.y; sz += v0.z; sw += v0.w;
    }

    float4 b4 = *(const float4*)&b[sub * 4];
    float4 o;
    o.x = fmaxf(dn * sx + b4.x, 0.0f);
    o.y = fmaxf(dn * sy + b4.y, 0.0f);
    o.z = fmaxf(dn * sz + b4.z, 0.0f);
    o.w = fmaxf(dn * sw + b4.w, 0.0f);
    ((float4*)g_acc)[(size_t)node * 16 + sub] = o;
}

// ---------------- pooling / head ---------------------------------------------
__global__ void mean_kernel(int n) {
    __shared__ float s[256];
    size_t total  = (size_t)n * F;
    size_t stride = (size_t)gridDim.x * blockDim.x;
    float acc = 0.0f;
    for (size_t i = (size_t)blockIdx.x * blockDim.x + threadIdx.x; i < total; i += stride)
        acc += g_acc[i];      // already relu'd
    s[threadIdx.x] = acc;
    __syncthreads();
    if (threadIdx.x < 64) {
        float v = s[threadIdx.x] + s[threadIdx.x + 64] +
                  s[threadIdx.x + 128] + s[threadIdx.x + 192];
        atomicAdd(&g_emb[threadIdx.x], v);
    }
}

__global__ void gfeat_kernel(const float* __restrict__ x, int n) {
    float s2 = 0, s3 = 0, s4 = 0, sm = 0, sl = 0, su = 0;
    int stride = gridDim.x * blockDim.x;
    for (int i = blockIdx.x * blockDim.x + threadIdx.x; i < n; i += stride) {
        const float* r = &x[(size_t)i * 5];
        float x0 = r[0], x1 = r[1], x2 = r[2], x3 = r[3], x4 = r[4];
        s2 += x2; s3 += x3; s4 += x4;
        float m = (x2 == 1.0f) ? 1.0f : 0.0f;
        sm += m; sl += x0 * m; su += x1 * m;
    }
#pragma unroll
    for (int o = 16; o > 0; o >>= 1) {
        s2 += __shfl_down_sync(0xffffffffu, s2, o);
        s3 += __shfl_down_sync(0xffffffffu, s3, o);
        s4 += __shfl_down_sync(0xffffffffu, s4, o);
        sm += __shfl_down_sync(0xffffffffu, sm, o);
        sl += __shfl_down_sync(0xffffffffu, sl, o);
        su += __shfl_down_sync(0xffffffffu, su, o);
    }
    if ((threadIdx.x & 31) == 0) {
        atomicAdd(&g_gf[0], s2); atomicAdd(&g_gf[1], s3);
        atomicAdd(&g_gf[2], s4); atomicAdd(&g_gf[3], sm);
        atomicAdd(&g_gf[4], sl); atomicAdd(&g_gf[5], su);
    }
}

__global__ void final_kernel(const float* __restrict__ Wp1,
                             const float* __restrict__ bp1,
                             const float* __restrict__ Wp2,
                             const float* __restrict__ bp2,
                             const int* __restrict__ Tp,
                             const int* __restrict__ Tmp,
                             float* __restrict__ out, int n) {
    __shared__ float e[71];
    __shared__ float hid[32];
    int tid = threadIdx.x;
    if (tid < 64) e[tid] = g_emb[tid] / (float)n;
    if (tid == 64) {
        float nAND = g_gf[1], nOR = g_gf[2];
        e[64] = g_gf[0];
        e[65] = nAND;
        e[66] = nOR;
        e[67] = nAND + nOR;
        float msum = g_gf[3];
        float safe = fmaxf(msum, 1.0f);
        e[68] = (msum > 0.0f) ? g_gf[4] / safe : 0.0f;
        e[69] = (msum > 0.0f) ? g_gf[5] / safe : 0.0f;
        e[70] = (float)(*Tp) / (float)(*Tmp);
    }
    __syncthreads();
    if (tid < 32) {
        float a = bp1[tid];
        for (int k = 0; k < 71; k++) a += e[k] * Wp1[k * 32 + tid];
        hid[tid] = fmaxf(a, 0.0f);
    }
    __syncthreads();
    if (tid < 2) {
        float r = bp2[tid];
#pragma unroll
        for (int j = 0; j < 32; j++) r += hid[j] * Wp2[j * 2 + tid];
        out[tid] = 2.0f + 4.0f / (1.0f + expf(-r));
    }
}

// ---------------- launch ------------------------------------------------------
extern "C" void kernel_launch(void* const* d_in, const int* in_sizes, int n_in,
                              void* d_out, int out_size) {
    const float* x   = (const float*)d_in[0];
    const void*  ei  = d_in[1];
    const float* W1  = (const float*)d_in[2];
    const float* b1  = (const float*)d_in[3];
    const float* W2  = (const float*)d_in[4];
    const float* b2  = (const float*)d_in[5];
    const float* Wp1 = (const float*)d_in[6];
    const float* bp1 = (const float*)d_in[7];
    const float* Wp2 = (const float*)d_in[8];
    const float* bp2 = (const float*)d_in[9];
    const int*   Tp  = (const int*)d_in[10];
    const int*   Tmp = (const int*)d_in[11];
    float* out = (float*)d_out;

    int n = in_sizes[0] / 5;
    int E = in_sizes[1] / 2;
    int nbScan = (n + SCAN_B - 1) / SCAN_B;

    // CSR build
    zero_kernel<<<(n + 255) / 256, 256>>>(n);
    detect_kernel<<<1, 1>>>((const unsigned int*)ei);
    count_kernel<<<(E + 255) / 256, 256>>>(ei, E, n);
    finalize_deg_kernel<<<(n + 255) / 256, 256>>>(n);
    scanA_kernel<<<nbScan, SCAN_B>>>(n);
    scanB_kernel<<<1, SCAN_B>>>(nbScan);
    scanC_kernel<<<nbScan, SCAN_B>>>(n, E);
    fill_kernel<<<(E + 255) / 256, 256>>>(ei, E, n);

    // layer 1
    xw1_kernel<<<(n + 3) / 4, 256>>>(x, W1, n);
    gather_kernel<<<(n + 15) / 16, 256>>>(b1, n);
    // layer 2
    xw2_kernel<<<(n + 63) / 64, 256>>>(W2, n);
    gather_kernel<<<(n + 15) / 16, 256>>>(b2, n);

    // pooling + head
    mean_kernel<<<296, 256>>>(n);
    gfeat_kernel<<<256, 256>>>(x, n);
    final_kernel<<<1, 128>>>(Wp1, bp1, Wp2, bp2, Tp, Tmp, out, n);
}

// round 3
// speedup vs baseline: 1.4688x; 1.1084x over previous
#include <cuda_runtime.h>
#include <cuda_fp16.h>
#include <math.h>

#define N_MAX 100000
#define E_MAX 1200000
#define F 64
#define SCAN_B 512
#define XW2_NODES 128

// ---------------- scratch (static device globals) --------------------------
__device__ __half g_xs [(size_t)N_MAX * F];  // dis[i]*(h@W) rows, fp16
__device__ float  g_acc[(size_t)N_MAX * F];  // relu'd layer-1 output (fp32)
__device__ int    g_deg[N_MAX];              // in-degree counts / fill cursor
__device__ int    g_off[N_MAX + 1];          // CSR offsets (by dst)
__device__ int    g_blk[SCAN_B];             // scan block sums
__device__ int    g_srcs[E_MAX];             // CSR src lists
__device__ float  g_dis[N_MAX];              // rsqrt(deg+1)
__device__ float  g_emb[F];                  // column sums for mean pool
__device__ float  g_gf [8];                  // global feature sums
__device__ int    g_is64;                    // edge_index dtype flag

// ---------------- helpers ---------------------------------------------------
__device__ __forceinline__ int load_dst(const void* eidx, int e, int E, int n) {
    int d = g_is64 ? (int)((const long long*)eidx)[(size_t)E + e]
                   : ((const int*)eidx)[E + e];
    return min(max(d, 0), n - 1);
}
__device__ __forceinline__ void load_edge(const void* eidx, int e, int E,
                                          int n, int& s, int& d) {
    if (g_is64) {
        const long long* p = (const long long*)eidx;
        s = (int)p[e];
        d = (int)p[(size_t)E + e];
    } else {
        const int* p = (const int*)eidx;
        s = p[e];
        d = p[E + e];
    }
    s = min(max(s, 0), n - 1);
    d = min(max(d, 0), n - 1);
}
__device__ __forceinline__ void acc8(float* s, uint4 r) {
    __half2* h = (__half2*)&r;
#pragma unroll
    for (int i = 0; i < 4; i++) {
        float2 f = __half22float2(h[i]);
        s[2 * i]     += f.x;
        s[2 * i + 1] += f.y;
    }
}

// ---------------- init: dtype detect + zero small arrays --------------------
__global__ void init_kernel(const unsigned int* p) {
    int tid = threadIdx.x;
    if (tid == 0) {
        int is64 = 1;
        for (int i = 1; i < 64; i += 2)
            if (p[i] != 0u) { is64 = 0; break; }
        g_is64 = is64;
    }
    if (tid < F) g_emb[tid] = 0.0f;
    if (tid < 8) g_gf[tid]  = 0.0f;
}

// ---------------- zero degree + global features over x ----------------------
__global__ void zerodeg_gfeat_kernel(const float* __restrict__ x, int n) {
    int i = blockIdx.x * blockDim.x + threadIdx.x;
    if (i < n) g_deg[i] = 0;

    float s2 = 0, s3 = 0, s4 = 0, sm = 0, sl = 0, su = 0;
    if (i < n) {
        const float* r = &x[(size_t)i * 5];
        float x0 = r[0], x1 = r[1];
        s2 = r[2]; s3 = r[3]; s4 = r[4];
        float m = (s2 == 1.0f) ? 1.0f : 0.0f;
        sm = m; sl = x0 * m; su = x1 * m;
    }
#pragma unroll
    for (int o = 16; o > 0; o >>= 1) {
        s2 += __shfl_down_sync(0xffffffffu, s2, o);
        s3 += __shfl_down_sync(0xffffffffu, s3, o);
        s4 += __shfl_down_sync(0xffffffffu, s4, o);
        sm += __shfl_down_sync(0xffffffffu, sm, o);
        sl += __shfl_down_sync(0xffffffffu, sl, o);
        su += __shfl_down_sync(0xffffffffu, su, o);
    }
    if ((threadIdx.x & 31) == 0) {
        atomicAdd(&g_gf[0], s2); atomicAdd(&g_gf[1], s3);
        atomicAdd(&g_gf[2], s4); atomicAdd(&g_gf[3], sm);
        atomicAdd(&g_gf[4], sl); atomicAdd(&g_gf[5], su);
    }
}

__global__ void count_kernel(const void* eidx, int E, int n) {
    int e = blockIdx.x * blockDim.x + threadIdx.x;
    if (e >= E) return;
    atomicAdd(&g_deg[load_dst(eidx, e, E, n)], 1);
}

// exclusive scan of g_deg into g_off (3-phase); also emits g_dis
__global__ void scanA_kernel(int n) {
    __shared__ int sh[SCAN_B];
    int tid = threadIdx.x;
    int i = blockIdx.x * SCAN_B + tid;
    int v = (i < n) ? g_deg[i] : 0;
    if (i < n) g_dis[i] = rsqrtf((float)v + 1.0f);
    sh[tid] = v;
    __syncthreads();
    for (int o = 1; o < SCAN_B; o <<= 1) {
        int t = (tid >= o) ? sh[tid - o] : 0;
        __syncthreads();
        sh[tid] += t;
        __syncthreads();
    }
    int incl = sh[tid];
    if (i < n) g_off[i] = incl - v;
    if (tid == SCAN_B - 1) g_blk[blockIdx.x] = incl;
}
__global__ void scanB_kernel(int nb) {
    __shared__ int sh[SCAN_B];
    int tid = threadIdx.x;
    int v = (tid < nb) ? g_blk[tid] : 0;
    sh[tid] = v;
    __syncthreads();
    for (int o = 1; o < SCAN_B; o <<= 1) {
        int t = (tid >= o) ? sh[tid - o] : 0;
        __syncthreads();
        sh[tid] += t;
        __syncthreads();
    }
    if (tid < nb) g_blk[tid] = sh[tid] - v;
}
__global__ void scanC_kernel(int n, int E) {
    int i = blockIdx.x * SCAN_B + threadIdx.x;
    if (i < n) {
        g_off[i] += g_blk[blockIdx.x];
        g_deg[i] = 0;
    }
    if (i == 0) g_off[n] = E;
}

__global__ void fill_kernel(const void* eidx, int E, int n) {
    int e = blockIdx.x * blockDim.x + threadIdx.x;
    if (e >= E) return;
    int s, d;
    load_edge(eidx, e, E, n, s, d);
    int idx = g_off[d] + atomicAdd(&g_deg[d], 1);
    g_srcs[idx] = s;
}

// ---------------- layer-1 transform: xs = dis*(x@W1) (fp16 out) -------------
__global__ void xw1_kernel(const float* __restrict__ x,
                           const float* __restrict__ W1, int n) {
    __shared__ float W1s[5 * F];
    __shared__ float xr[4 * 5];
    int base = blockIdx.x * 4;
    int tid  = threadIdx.x;
    for (int i = tid; i < 5 * F; i += 256) W1s[i] = W1[i];
    if (tid < 20) {
        int node = base + tid / 5;
        xr[tid] = (node < n) ? x[(size_t)node * 5 + (tid % 5)] : 0.0f;
    }
    __syncthreads();
    int nl   = tid >> 6;
    int col  = tid & 63;
    int node = base + nl;
    if (node >= n) return;
    float s = 0.0f;
#pragma unroll
    for (int k = 0; k < 5; k++) s += xr[nl * 5 + k] * W1s[k * F + col];
    g_xs[(size_t)node * F + col] = __float2half_rn(g_dis[node] * s);
}

// ---------------- layer-2 transform: xs = dis*(acc@W2) (fp16 out) -----------
// persistent grid-stride over 128-node tiles; 128 threads; 8n x 8c per thread
__global__ void xw2_kernel(const float* __restrict__ W2, int n, int nTiles) {
    __shared__ float W2s[F * F];            // 16 KB
    __shared__ float hs [XW2_NODES * F];    // 32 KB
    int tid = threadIdx.x;

    for (int i = tid; i < (F * F) / 4; i += 128)
        ((float4*)W2s)[i] = ((const float4*)W2)[i];

    int cg = tid & 7;     // cols cg*8 .. cg*8+7
    int ng = tid >> 3;    // node group: nodes ng*8 .. ng*8+7 within tile

    for (int tile = blockIdx.x; tile < nTiles; tile += gridDim.x) {
        int base = tile * XW2_NODES;
        __syncthreads();   // hs reuse guard (also orders W2 load on iter 0)
        for (int i = tid; i < XW2_NODES * 16; i += 128) {
            int node = base + (i >> 4);
            float4 v = make_float4(0.f, 0.f, 0.f, 0.f);
            if (node < n) v = ((const float4*)g_acc)[(size_t)node * 16 + (i & 15)];
            ((float4*)hs)[i] = v;
        }
        __syncthreads();

        float a[8][8];
#pragma unroll
        for (int i = 0; i < 8; i++)
#pragma unroll
            for (int j = 0; j < 8; j++) a[i][j] = 0.0f;

        const float4* hsv = (const float4*)hs;
        const float4* Wv  = (const float4*)W2s;
#pragma unroll 4
        for (int k4 = 0; k4 < 16; k4++) {
            float4 hv[8];
#pragma unroll
            for (int i = 0; i < 8; i++) hv[i] = hsv[(ng * 8 + i) * 16 + k4];
#pragma unroll
            for (int kk = 0; kk < 4; kk++) {
                float4 wA = Wv[(k4 * 4 + kk) * 16 + cg * 2];
                float4 wB = Wv[(k4 * 4 + kk) * 16 + cg * 2 + 1];
#pragma unroll
                for (int i = 0; i < 8; i++) {
                    float h = (kk == 0) ? hv[i].x : (kk == 1) ? hv[i].y
                            : (kk == 2) ? hv[i].z : hv[i].w;
                    a[i][0] += h * wA.x; a[i][1] += h * wA.y;
                    a[i][2] += h * wA.z; a[i][3] += h * wA.w;
                    a[i][4] += h * wB.x; a[i][5] += h * wB.y;
                    a[i][6] += h * wB.z; a[i][7] += h * wB.w;
                }
            }
        }

#pragma unroll
        for (int i = 0; i < 8; i++) {
            int node = base + ng * 8 + i;
            if (node >= n) continue;
            float dn = g_dis[node];
            __half2 h4[4];
#pragma unroll
            for (int j = 0; j < 4; j++)
                h4[j] = __floats2half2_rn(a[i][2 * j] * dn, a[i][2 * j + 1] * dn);
            *(uint4*)&g_xs[(size_t)node * F + cg * 8] = *(uint4*)h4;
        }
    }
}

// ---------------- CSR gather, layer 1: acc = relu(dis*sum + b) --------------
// 8 lanes/node (16B of fp16 each), 32 nodes per 256-thread block.
__global__ void gather1_kernel(const float* __restrict__ b, int n) {
    int tid  = threadIdx.x;
    int sub  = tid & 7;
    int node = blockIdx.x * 32 + (tid >> 3);
    if (node >= n) return;

    const uint4* xsv = (const uint4*)g_xs;
    int beg = g_off[node], end = g_off[node + 1];
    float dn = g_dis[node];

    float s[8] = {0, 0, 0, 0, 0, 0, 0, 0};
    acc8(s, xsv[(size_t)node * 8 + sub]);   // self term

    int e = beg;
    for (; e + 2 <= end; e += 2) {
        int s0 = g_srcs[e], s1 = g_srcs[e + 1];
        uint4 r0 = xsv[(size_t)s0 * 8 + sub];
        uint4 r1 = xsv[(size_t)s1 * 8 + sub];
        acc8(s, r0);
        acc8(s, r1);
    }
    if (e < end) acc8(s, xsv[(size_t)g_srcs[e] * 8 + sub]);

    float4 b0 = ((const float4*)b)[sub * 2];
    float4 b1 = ((const float4*)b)[sub * 2 + 1];
    float4 o0, o1;
    o0.x = fmaxf(dn * s[0] + b0.x, 0.f); o0.y = fmaxf(dn * s[1] + b0.y, 0.f);
    o0.z = fmaxf(dn * s[2] + b0.z, 0.f); o0.w = fmaxf(dn * s[3] + b0.w, 0.f);
    o1.x = fmaxf(dn * s[4] + b1.x, 0.f); o1.y = fmaxf(dn * s[5] + b1.y, 0.f);
    o1.z = fmaxf(dn * s[6] + b1.z, 0.f); o1.w = fmaxf(dn * s[7] + b1.w, 0.f);
    ((float4*)g_acc)[(size_t)node * 16 + sub * 2]     = o0;
    ((float4*)g_acc)[(size_t)node * 16 + sub * 2 + 1] = o1;
}

// ---------------- CSR gather, layer 2 + fused mean pool ---------------------
__global__ void gather2_kernel(const float* __restrict__ b, int n) {
    __shared__ float colsum[F];
    int tid  = threadIdx.x;
    int sub  = tid & 7;
    int node = blockIdx.x * 32 + (tid >> 3);
    bool valid = node < n;

    if (tid < F) colsum[tid] = 0.0f;
    __syncthreads();

    float s[8] = {0, 0, 0, 0, 0, 0, 0, 0};
    float dn = 0.0f;
    if (valid) {
        const uint4* xsv = (const uint4*)g_xs;
        int beg = g_off[node], end = g_off[node + 1];
        dn = g_dis[node];
        acc8(s, xsv[(size_t)node * 8 + sub]);   // self term
        int e = beg;
        for (; e + 2 <= end; e += 2) {
            int s0 = g_srcs[e], s1 = g_srcs[e + 1];
            uint4 r0 = xsv[(size_t)s0 * 8 + sub];
            uint4 r1 = xsv[(size_t)s1 * 8 + sub];
            acc8(s, r0);
            acc8(s, r1);
        }
        if (e < end) acc8(s, xsv[(size_t)g_srcs[e] * 8 + sub]);
    }

    float4 b0 = ((const float4*)b)[sub * 2];
    float4 b1 = ((const float4*)b)[sub * 2 + 1];
    const float* bb = (const float*)&b0;      // b0,b1 contiguous? use array
    float bv[8] = {b0.x, b0.y, b0.z, b0.w, b1.x, b1.y, b1.z, b1.w};
    (void)bb;

#pragma unroll
    for (int j = 0; j < 8; j++) {
        float v = valid ? fmaxf(dn * s[j] + bv[j], 0.0f) : 0.0f;
        v += __shfl_down_sync(0xffffffffu, v, 16);
        v += __shfl_down_sync(0xffffffffu, v, 8);
        if ((tid & 31) < 8) atomicAdd(&colsum[sub * 8 + j], v);
    }
    __syncthreads();
    if (tid < F) atomicAdd(&g_emb[tid], colsum[tid]);
}

// ---------------- final MLP head ---------------------------------------------
__global__ void final_kernel(const float* __restrict__ Wp1,
                             const float* __restrict__ bp1,
                             const float* __restrict__ Wp2,
                             const float* __restrict__ bp2,
                             const int* __restrict__ Tp,
                             const int* __restrict__ Tmp,
                             float* __restrict__ out, int n) {
    __shared__ float e[71];
    __shared__ float hid[32];
    int tid = threadIdx.x;
    if (tid < 64) e[tid] = g_emb[tid] / (float)n;
    if (tid == 64) {
        float nAND = g_gf[1], nOR = g_gf[2];
        e[64] = g_gf[0];
        e[65] = nAND;
        e[66] = nOR;
        e[67] = nAND + nOR;
        float msum = g_gf[3];
        float safe = fmaxf(msum, 1.0f);
        e[68] = (msum > 0.0f) ? g_gf[4] / safe : 0.0f;
        e[69] = (msum > 0.0f) ? g_gf[5] / safe : 0.0f;
        e[70] = (float)(*Tp) / (float)(*Tmp);
    }
    __syncthreads();
    if (tid < 32) {
        float a = bp1[tid];
        for (int k = 0; k < 71; k++) a += e[k] * Wp1[k * 32 + tid];
        hid[tid] = fmaxf(a, 0.0f);
    }
    __syncthreads();
    if (tid < 2) {
        float r = bp2[tid];
#pragma unroll
        for (int j = 0; j < 32; j++) r += hid[j] * Wp2[j * 2 + tid];
        out[tid] = 2.0f + 4.0f / (1.0f + expf(-r));
    }
}

// ---------------- launch ------------------------------------------------------
extern "C" void kernel_launch(void* const* d_in, const int* in_sizes, int n_in,
                              void* d_out, int out_size) {
    const float* x   = (const float*)d_in[0];
    const void*  ei  = d_in[1];
    const float* W1  = (const float*)d_in[2];
    const float* b1  = (const float*)d_in[3];
    const float* W2  = (const float*)d_in[4];
    const float* b2  = (const float*)d_in[5];
    const float* Wp1 = (const float*)d_in[6];
    const float* bp1 = (const float*)d_in[7];
    const float* Wp2 = (const float*)d_in[8];
    const float* bp2 = (const float*)d_in[9];
    const int*   Tp  = (const int*)d_in[10];
    const int*   Tmp = (const int*)d_in[11];
    float* out = (float*)d_out;

    int n = in_sizes[0] / 5;
    int E = in_sizes[1] / 2;
    int nbScan = (n + SCAN_B - 1) / SCAN_B;
    int nTiles = (n + XW2_NODES - 1) / XW2_NODES;

    // init + CSR build
    init_kernel<<<1, 128>>>((const unsigned int*)ei);
    zerodeg_gfeat_kernel<<<(n + 255) / 256, 256>>>(x, n);
    count_kernel<<<(E + 255) / 256, 256>>>(ei, E, n);
    scanA_kernel<<<nbScan, SCAN_B>>>(n);
    scanB_kernel<<<1, SCAN_B>>>(nbScan);
    scanC_kernel<<<nbScan, SCAN_B>>>(n, E);
    fill_kernel<<<(E + 255) / 256, 256>>>(ei, E, n);

    // layer 1
    xw1_kernel<<<(n + 3) / 4, 256>>>(x, W1, n);
    gather1_kernel<<<(n + 31) / 32, 256>>>(b1, n);
    // layer 2 (+ fused mean pool)
    xw2_kernel<<<592, 128>>>(W2, n, nTiles);
    gather2_kernel<<<(n + 31) / 32, 256>>>(b2, n);

    // head
    final_kernel<<<1, 128>>>(Wp1, bp1, Wp2, bp2, Tp, Tmp, out, n);
}

// round 4
// speedup vs baseline: 1.9678x; 1.3397x over previous
#include <cuda_runtime.h>
#include <cuda_fp16.h>
#include <math.h>

#define N_MAX 100000
#define E_MAX 1200000
#define F 64
#define SCAN_B 512
#define PRE_B 256
#define MAXPRE ((N_MAX + PRE_B - 1) / PRE_B)

// ---------------- scratch (static device globals) --------------------------
__device__ __half g_xs [(size_t)N_MAX * F];  // dis[i]*(h@W) rows, fp16
__device__ __half g_h  [(size_t)N_MAX * F];  // relu'd layer-1 output, fp16
__device__ int    g_deg[N_MAX];              // in-degree counts / fill cursor
__device__ int    g_off[N_MAX + 1];          // CSR offsets (by dst)
__device__ int    g_blk[SCAN_B];             // scan block aggregates
__device__ int    g_srcs[E_MAX];             // CSR src lists
__device__ float  g_dis[N_MAX];              // rsqrt(deg+1)
__device__ float  g_emb[F];                  // column sums for mean pool
__device__ float  g_gfp[MAXPRE * 8];         // per-block global-feature partials
__device__ int    g_is64;                    // edge_index dtype flag

// ---------------- helpers ---------------------------------------------------
__device__ __forceinline__ int load_dst(const void* eidx, int e, int E, int n) {
    int d = g_is64 ? (int)((const long long*)eidx)[(size_t)E + e]
                   : ((const int*)eidx)[E + e];
    return min(max(d, 0), n - 1);
}
__device__ __forceinline__ void load_edge(const void* eidx, int e, int E,
                                          int n, int& s, int& d) {
    if (g_is64) {
        const long long* p = (const long long*)eidx;
        s = (int)p[e];
        d = (int)p[(size_t)E + e];
    } else {
        const int* p = (const int*)eidx;
        s = p[e];
        d = p[E + e];
    }
    s = min(max(s, 0), n - 1);
    d = min(max(d, 0), n - 1);
}
__device__ __forceinline__ void acc8(float* s, uint4 r) {
    __half2* h = (__half2*)&r;
#pragma unroll
    for (int i = 0; i < 4; i++) {
        float2 f = __half22float2(h[i]);
        s[2 * i]     += f.x;
        s[2 * i + 1] += f.y;
    }
}

// ---------------- pre: zero deg, detect dtype, gfeat partials, zero emb -----
__global__ void pre_kernel(const float* __restrict__ x,
                           const unsigned int* __restrict__ p, int n) {
    __shared__ float sw[8][6];
    int tid = threadIdx.x;
    int i = blockIdx.x * PRE_B + tid;
    if (i < n) g_deg[i] = 0;
    if (blockIdx.x == 0) {
        if (tid < F) g_emb[tid] = 0.0f;
        if (tid == PRE_B - 1) {
            int is64 = 1;
            for (int k = 1; k < 64; k += 2)
                if (p[k] != 0u) { is64 = 0; break; }
            g_is64 = is64;
        }
    }
    float s2 = 0, s3 = 0, s4 = 0, sm = 0, sl = 0, su = 0;
    if (i < n) {
        const float* r = &x[(size_t)i * 5];
        float x0 = r[0], x1 = r[1];
        s2 = r[2]; s3 = r[3]; s4 = r[4];
        float m = (s2 == 1.0f) ? 1.0f : 0.0f;
        sm = m; sl = x0 * m; su = x1 * m;
    }
#pragma unroll
    for (int o = 16; o > 0; o >>= 1) {
        s2 += __shfl_down_sync(0xffffffffu, s2, o);
        s3 += __shfl_down_sync(0xffffffffu, s3, o);
        s4 += __shfl_down_sync(0xffffffffu, s4, o);
        sm += __shfl_down_sync(0xffffffffu, sm, o);
        sl += __shfl_down_sync(0xffffffffu, sl, o);
        su += __shfl_down_sync(0xffffffffu, su, o);
    }
    int w = tid >> 5;
    if ((tid & 31) == 0) {
        sw[w][0] = s2; sw[w][1] = s3; sw[w][2] = s4;
        sw[w][3] = sm; sw[w][4] = sl; sw[w][5] = su;
    }
    __syncthreads();
    if (tid < 6) {
        float acc = 0.0f;
#pragma unroll
        for (int q = 0; q < 8; q++) acc += sw[q][tid];
        g_gfp[blockIdx.x * 8 + tid] = acc;
    }
}

__global__ void count_kernel(const void* eidx, int E, int n) {
    int e = blockIdx.x * blockDim.x + threadIdx.x;
    if (e >= E) return;
    atomicAdd(&g_deg[load_dst(eidx, e, E, n)], 1);
}

// local exclusive scan per block; publish block aggregate; emit g_dis
__global__ void scanA_kernel(int n) {
    __shared__ int sh[SCAN_B];
    int tid = threadIdx.x;
    int i = blockIdx.x * SCAN_B + tid;
    int v = (i < n) ? g_deg[i] : 0;
    if (i < n) g_dis[i] = rsqrtf((float)v + 1.0f);
    sh[tid] = v;
    __syncthreads();
    for (int o = 1; o < SCAN_B; o <<= 1) {
        int t = (tid >= o) ? sh[tid - o] : 0;
        __syncthreads();
        sh[tid] += t;
        __syncthreads();
    }
    int incl = sh[tid];
    if (i < n) g_off[i] = incl - v;
    if (tid == SCAN_B - 1) g_blk[blockIdx.x] = incl;
}

// finalize: each block sums aggregates of preceding blocks itself
__global__ void scanC_kernel(int n, int E) {
    __shared__ int sh[16];
    __shared__ int pre_s;
    int tid = threadIdx.x;
    int bid = blockIdx.x;
    int acc = 0;
    for (int j = tid; j < bid; j += SCAN_B) acc += g_blk[j];
#pragma unroll
    for (int o = 16; o > 0; o >>= 1)
        acc += __shfl_down_sync(0xffffffffu, acc, o);
    if ((tid & 31) == 0) sh[tid >> 5] = acc;
    __syncthreads();
    if (tid == 0) {
        int s = 0;
#pragma unroll
        for (int q = 0; q < 16; q++) s += sh[q];
        pre_s = s;
    }
    __syncthreads();
    int i = bid * SCAN_B + tid;
    if (i < n) {
        g_off[i] += pre_s;
        g_deg[i] = 0;                       // reset as fill cursor
    }
    if (bid == 0 && tid == 0) g_off[n] = E;
}

__global__ void fill_kernel(const void* eidx, int E, int n) {
    int e = blockIdx.x * blockDim.x + threadIdx.x;
    if (e >= E) return;
    int s, d;
    load_edge(eidx, e, E, n, s, d);
    int idx = g_off[d] + atomicAdd(&g_deg[d], 1);
    g_srcs[idx] = s;
}

// ---------------- layer-1 transform: xs = dis*(x@W1) (fp16 out) -------------
__global__ void xw1_kernel(const float* __restrict__ x,
                           const float* __restrict__ W1, int n) {
    __shared__ float W1s[5 * F];
    __shared__ float xr[4 * 5];
    int base = blockIdx.x * 4;
    int tid  = threadIdx.x;
    for (int i = tid; i < 5 * F; i += 256) W1s[i] = W1[i];
    if (tid < 20) {
        int node = base + tid / 5;
        xr[tid] = (node < n) ? x[(size_t)node * 5 + (tid % 5)] : 0.0f;
    }
    __syncthreads();
    int nl   = tid >> 6;
    int col  = tid & 63;
    int node = base + nl;
    if (node >= n) return;
    float s = 0.0f;
#pragma unroll
    for (int k = 0; k < 5; k++) s += xr[nl * 5 + k] * W1s[k * F + col];
    g_xs[(size_t)node * F + col] = __float2half_rn(g_dis[node] * s);
}

// ---------------- CSR gather, layer 1: h = relu(dis*sum + b) (fp16 out) -----
__global__ void gather1_kernel(const float* __restrict__ b, int n) {
    int tid  = threadIdx.x;
    int sub  = tid & 7;
    int node = blockIdx.x * 32 + (tid >> 3);
    if (node >= n) return;

    const uint4* xsv = (const uint4*)g_xs;
    int beg = g_off[node], end = g_off[node + 1];
    float dn = g_dis[node];

    float s[8] = {0, 0, 0, 0, 0, 0, 0, 0};
    acc8(s, xsv[(size_t)node * 8 + sub]);   // self term

    int e = beg;
    for (; e + 4 <= end; e += 4) {
        int s0 = g_srcs[e],     s1 = g_srcs[e + 1];
        int s2 = g_srcs[e + 2], s3 = g_srcs[e + 3];
        uint4 r0 = xsv[(size_t)s0 * 8 + sub];
        uint4 r1 = xsv[(size_t)s1 * 8 + sub];
        uint4 r2 = xsv[(size_t)s2 * 8 + sub];
        uint4 r3 = xsv[(size_t)s3 * 8 + sub];
        acc8(s, r0); acc8(s, r1); acc8(s, r2); acc8(s, r3);
    }
    for (; e < end; e++) acc8(s, xsv[(size_t)g_srcs[e] * 8 + sub]);

    float4 b0 = ((const float4*)b)[sub * 2];
    float4 b1 = ((const float4*)b)[sub * 2 + 1];
    float bv[8] = {b0.x, b0.y, b0.z, b0.w, b1.x, b1.y, b1.z, b1.w};
    __half2 oh[4];
#pragma unroll
    for (int j = 0; j < 4; j++)
        oh[j] = __floats2half2_rn(fmaxf(dn * s[2 * j]     + bv[2 * j],     0.f),
                                  fmaxf(dn * s[2 * j + 1] + bv[2 * j + 1], 0.f));
    *(uint4*)&g_h[(size_t)node * F + sub * 8] = *(uint4*)oh;
}

// ---------------- layer-2 transform via tensor cores ------------------------
// xs = dis*(h @ W2), h fp16, mma.sync m16n8k16 fp16->fp32. 128 nodes/block.
#define HS_STR 72
__global__ void xw2_kernel(const float* __restrict__ W2, int n) {
    __shared__ __half hs [128 * HS_STR];
    __shared__ __half w2t[F * HS_STR];
    int tid  = threadIdx.x;
    int base = blockIdx.x * 128;

    // W2 [k][c] fp32 -> w2t [c][k] fp16
    for (int idx = tid; idx < F * F; idx += 256) {
        int k = idx >> 6, c = idx & 63;
        w2t[c * HS_STR + k] = __float2half_rn(W2[idx]);
    }
    // h tile -> hs (rows padded to HS_STR halfs)
    for (int idx = tid; idx < 128 * 8; idx += 256) {
        int nl = idx >> 3, q = idx & 7;
        int node = base + nl;
        uint4 v = make_uint4(0u, 0u, 0u, 0u);
        if (node < n) v = *(const uint4*)&g_h[(size_t)node * F + q * 8];
        *(uint4*)&hs[nl * HS_STR + q * 8] = v;
    }
    __syncthreads();

    int w    = tid >> 5;
    int lane = tid & 31;
    int g    = lane >> 2;
    int t    = lane & 3;
    int r0   = w * 16 + g;

    float d[8][4];
#pragma unroll
    for (int ct = 0; ct < 8; ct++)
#pragma unroll
        for (int j = 0; j < 4; j++) d[ct][j] = 0.0f;

#pragma unroll
    for (int kc = 0; kc < 4; kc++) {
        int kb = kc * 16 + 2 * t;
        unsigned a0 = *(const unsigned*)&hs[(size_t)r0       * HS_STR + kb];
        unsigned a1 = *(const unsigned*)&hs[(size_t)(r0 + 8) * HS_STR + kb];
        unsigned a2 = *(const unsigned*)&hs[(size_t)r0       * HS_STR + kb + 8];
        unsigned a3 = *(const unsigned*)&hs[(size_t)(r0 + 8) * HS_STR + kb + 8];
#pragma unroll
        for (int ct = 0; ct < 8; ct++) {
            int c = ct * 8 + g;
            unsigned b0 = *(const unsigned*)&w2t[c * HS_STR + kb];
            unsigned b1 = *(const unsigned*)&w2t[c * HS_STR + kb + 8];
            asm volatile(
                "mma.sync.aligned.m16n8k16.row.col.f32.f16.f16.f32 "
                "{%0,%1,%2,%3},{%4,%5,%6,%7},{%8,%9},{%0,%1,%2,%3};\n"
                : "+f"(d[ct][0]), "+f"(d[ct][1]), "+f"(d[ct][2]), "+f"(d[ct][3])
                : "r"(a0), "r"(a1), "r"(a2), "r"(a3), "r"(b0), "r"(b1));
        }
    }

    int node0 = base + r0;
    int node1 = node0 + 8;
    float dn0 = (node0 < n) ? g_dis[node0] : 0.0f;
    float dn1 = (node1 < n) ? g_dis[node1] : 0.0f;
#pragma unroll
    for (int ct = 0; ct < 8; ct++) {
        int c = ct * 8 + 2 * t;
        if (node0 < n)
            *(__half2*)&g_xs[(size_t)node0 * F + c] =
                __floats2half2_rn(d[ct][0] * dn0, d[ct][1] * dn0);
        if (node1 < n)
            *(__half2*)&g_xs[(size_t)node1 * F + c] =
                __floats2half2_rn(d[ct][2] * dn1, d[ct][3] * dn1);
    }
}

// ---------------- CSR gather, layer 2 + fused mean pool ---------------------
__global__ void gather2_kernel(const float* __restrict__ b, int n) {
    __shared__ float colsum[F];
    int tid  = threadIdx.x;
    int sub  = tid & 7;
    int node = blockIdx.x * 32 + (tid >> 3);
    bool valid = node < n;

    if (tid < F) colsum[tid] = 0.0f;
    __syncthreads();

    float s[8] = {0, 0, 0, 0, 0, 0, 0, 0};
    float dn = 0.0f;
    if (valid) {
        const uint4* xsv = (const uint4*)g_xs;
        int beg = g_off[node], end = g_off[node + 1];
        dn = g_dis[node];
        acc8(s, xsv[(size_t)node * 8 + sub]);
        int e = beg;
        for (; e + 4 <= end; e += 4) {
            int s0 = g_srcs[e],     s1 = g_srcs[e + 1];
            int s2 = g_srcs[e + 2], s3 = g_srcs[e + 3];
            uint4 r0 = xsv[(size_t)s0 * 8 + sub];
            uint4 r1 = xsv[(size_t)s1 * 8 + sub];
            uint4 r2 = xsv[(size_t)s2 * 8 + sub];
            uint4 r3 = xsv[(size_t)s3 * 8 + sub];
            acc8(s, r0); acc8(s, r1); acc8(s, r2); acc8(s, r3);
        }
        for (; e < end; e++) acc8(s, xsv[(size_t)g_srcs[e] * 8 + sub]);
    }

    float4 b0 = ((const float4*)b)[sub * 2];
    float4 b1 = ((const float4*)b)[sub * 2 + 1];
    float bv[8] = {b0.x, b0.y, b0.z, b0.w, b1.x, b1.y, b1.z, b1.w};

#pragma unroll
    for (int j = 0; j < 8; j++) {
        float v = valid ? fmaxf(dn * s[j] + bv[j], 0.0f) : 0.0f;
        v += __shfl_down_sync(0xffffffffu, v, 16);
        v += __shfl_down_sync(0xffffffffu, v, 8);
        if ((tid & 31) < 8) atomicAdd(&colsum[sub * 8 + j], v);
    }
    __syncthreads();
    if (tid < F) atomicAdd(&g_emb[tid], colsum[tid]);
}

// ---------------- final MLP head ---------------------------------------------
__global__ void final_kernel(const float* __restrict__ Wp1,
                             const float* __restrict__ bp1,
                             const float* __restrict__ Wp2,
                             const float* __restrict__ bp2,
                             const int* __restrict__ Tp,
                             const int* __restrict__ Tmp,
                             float* __restrict__ out, int n, int nbPre) {
    __shared__ float e[71];
    __shared__ float hid[32];
    __shared__ float gf6[6];
    int tid = threadIdx.x;
    if (tid < 64) e[tid] = g_emb[tid] / (float)n;

    int w = tid >> 5, lane = tid & 31;
    if (w < 6) {
        float s = 0.0f;
        for (int bb = lane; bb < nbPre; bb += 32) s += g_gfp[bb * 8 + w];
#pragma unroll
        for (int o = 16; o > 0; o >>= 1)
            s += __shfl_down_sync(0xffffffffu, s, o);
        if (lane == 0) gf6[w] = s;
    }
    __syncthreads();
    if (tid == 64) {
        float nAND = gf6[1], nOR = gf6[2];
        e[64] = gf6[0];
        e[65] = nAND;
        e[66] = nOR;
        e[67] = nAND + nOR;
        float msum = gf6[3];
        float safe = fmaxf(msum, 1.0f);
        e[68] = (msum > 0.0f) ? gf6[4] / safe : 0.0f;
        e[69] = (msum > 0.0f) ? gf6[5] / safe : 0.0f;
        e[70] = (float)(*Tp) / (float)(*Tmp);
    }
    __syncthreads();
    if (tid < 32) {
        float a = bp1[tid];
        for (int k = 0; k < 71; k++) a += e[k] * Wp1[k * 32 + tid];
        hid[tid] = fmaxf(a, 0.0f);
    }
    __syncthreads();
    if (tid < 2) {
        float r = bp2[tid];
#pragma unroll
        for (int j = 0; j < 32; j++) r += hid[j] * Wp2[j * 2 + tid];
        out[tid] = 2.0f + 4.0f / (1.0f + expf(-r));
    }
}

// ---------------- launch ------------------------------------------------------
extern "C" void kernel_launch(void* const* d_in, const int* in_sizes, int n_in,
                              void* d_out, int out_size) {
    const float* x   = (const float*)d_in[0];
    const void*  ei  = d_in[1];
    const float* W1  = (const float*)d_in[2];
    const float* b1  = (const float*)d_in[3];
    const float* W2  = (const float*)d_in[4];
    const float* b2  = (const float*)d_in[5];
    const float* Wp1 = (const float*)d_in[6];
    const float* bp1 = (const float*)d_in[7];
    const float* Wp2 = (const float*)d_in[8];
    const float* bp2 = (const float*)d_in[9];
    const int*   Tp  = (const int*)d_in[10];
    const int*   Tmp = (const int*)d_in[11];
    float* out = (float*)d_out;

    int n = in_sizes[0] / 5;
    int E = in_sizes[1] / 2;
    int nbPre  = (n + PRE_B - 1) / PRE_B;
    int nbScan = (n + SCAN_B - 1) / SCAN_B;
    int nTiles = (n + 127) / 128;

    pre_kernel<<<nbPre, PRE_B>>>(x, (const unsigned int*)ei, n);
    count_kernel<<<(E + 255) / 256, 256>>>(ei, E, n);
    scanA_kernel<<<nbScan, SCAN_B>>>(n);
    scanC_kernel<<<nbScan, SCAN_B>>>(n, E);
    fill_kernel<<<(E + 255) / 256, 256>>>(ei, E, n);

    xw1_kernel<<<(n + 3) / 4, 256>>>(x, W1, n);
    gather1_kernel<<<(n + 31) / 32, 256>>>(b1, n);
    xw2_kernel<<<nTiles, 256>>>(W2, n);
    gather2_kernel<<<(n + 31) / 32, 256>>>(b2, n);

    final_kernel<<<1, 192>>>(Wp1, bp1, Wp2, bp2, Tp, Tmp, out, n, nbPre);
}